// round 6
// baseline (speedup 1.0000x reference)
#include <cuda_runtime.h>
#include <mma.h>
#include <cstdint>

using namespace nvcuda;

#define NN 100000
#define NP 100032            // padded to multiple of 64
#define DD 128
#define KK 512               // R*DD stacked K dim
#define EE 1600000
#define RR 4

#define SCAN_N   (RR * NN)
#define SCAN_BLK 512
#define SCAN_NBLK ((SCAN_N + SCAN_BLK - 1) / SCAN_BLK)

// ---------------- device scratch --------------------------------------------
__device__ float  g_agg[(size_t)NP * KK];      // [n][r*128+k] aggregates (204MB)
__device__ float  g_h1[(size_t)NN * DD];       // layer-1 output
__device__ int    g_degout[SCAN_N];
__device__ int    g_degin[SCAN_N];
__device__ float  g_rdout[SCAN_N];
__device__ float  g_rdin[SCAN_N];
__device__ int    g_off[SCAN_N];
__device__ int    g_cur[SCAN_N];
__device__ int    g_bsum[SCAN_NBLK];
__device__ float2 g_csr[(size_t)RR * EE];      // (src bits, weight), grouped by (r,dst)

// ---------------- setup kernels ---------------------------------------------

__global__ void zero_deg_kernel() {
    int i = blockIdx.x * blockDim.x + threadIdx.x;
    if (i < SCAN_N) { g_degout[i] = 0; g_degin[i] = 0; }
}

__global__ void deg_kernel(const int* __restrict__ src, const int* __restrict__ dst) {
    long long i = (long long)blockIdx.x * blockDim.x + threadIdx.x;
    if (i >= (long long)RR * EE) return;
    int r = (int)(i / EE);
    atomicAdd(&g_degout[r * NN + src[i]], 1);
    atomicAdd(&g_degin[r * NN + dst[i]], 1);
}

__global__ void rsqrt_kernel() {
    int i = blockIdx.x * blockDim.x + threadIdx.x;
    if (i >= SCAN_N) return;
    g_rdout[i] = rsqrtf(fmaxf((float)g_degout[i], 1.f));
    g_rdin[i]  = rsqrtf(fmaxf((float)g_degin[i], 1.f));
}

__global__ void scan_a_kernel() {
    __shared__ int s[SCAN_BLK];
    int i = blockIdx.x * SCAN_BLK + threadIdx.x;
    s[threadIdx.x] = (i < SCAN_N) ? g_degin[i] : 0;
    __syncthreads();
    for (int d = SCAN_BLK / 2; d > 0; d >>= 1) {
        if (threadIdx.x < d) s[threadIdx.x] += s[threadIdx.x + d];
        __syncthreads();
    }
    if (threadIdx.x == 0) g_bsum[blockIdx.x] = s[0];
}

__global__ void scan_b_kernel() {
    __shared__ int s[1024];
    int t = threadIdx.x;
    s[t] = (t < SCAN_NBLK) ? g_bsum[t] : 0;
    __syncthreads();
    for (int d = 1; d < 1024; d <<= 1) {
        int v = (t >= d) ? s[t - d] : 0;
        __syncthreads();
        s[t] += v;
        __syncthreads();
    }
    if (t < SCAN_NBLK) g_bsum[t] = (t == 0) ? 0 : s[t - 1];
}

__global__ void scan_c_kernel() {
    __shared__ int s[SCAN_BLK];
    int i = blockIdx.x * SCAN_BLK + threadIdx.x;
    int v = (i < SCAN_N) ? g_degin[i] : 0;
    s[threadIdx.x] = v;
    __syncthreads();
    for (int d = 1; d < SCAN_BLK; d <<= 1) {
        int u = (threadIdx.x >= d) ? s[threadIdx.x - d] : 0;
        __syncthreads();
        s[threadIdx.x] += u;
        __syncthreads();
    }
    if (i < SCAN_N) {
        int ex = s[threadIdx.x] - v + g_bsum[blockIdx.x];
        g_off[i] = ex;
        g_cur[i] = ex;
    }
}

__global__ void fill_kernel(const int* __restrict__ src, const int* __restrict__ dst,
                            const float* __restrict__ ew) {
    long long i = (long long)blockIdx.x * blockDim.x + threadIdx.x;
    if (i >= (long long)RR * EE) return;
    int r = (int)(i / EE);
    int s = src[i], d = dst[i];
    float w = ew[i] * g_rdout[r * NN + s] * g_rdin[r * NN + d];
    int p = atomicAdd(&g_cur[r * NN + d], 1);
    g_csr[p] = make_float2(__int_as_float(s), w);
}

// ---------------- pull: agg[n][r*128+c] = sum_e w * h[src][c]  (all 4 rel) ---
// One warp per node; lane owns 4 columns. Gather source h stays L2-resident;
// csr read streaming; agg written streaming (evict-first).
__global__ __launch_bounds__(256) void pull_all_kernel(const float* __restrict__ h)
{
    int warp = (blockIdx.x * blockDim.x + threadIdx.x) >> 5;
    int lane = threadIdx.x & 31;
    if (warp >= NP) return;
    int n = warp;
    const int co = lane * 4;
    float* aggrow = g_agg + (size_t)n * KK;

    if (n >= NN) {   // pad rows: zero so the GEMM reads clean data
#pragma unroll
        for (int r = 0; r < RR; r++)
            __stcs((float4*)(aggrow + r * DD + co), make_float4(0.f, 0.f, 0.f, 0.f));
        return;
    }

#pragma unroll
    for (int r = 0; r < RR; r++) {
        int idx = r * NN + n;
        const float2* eb = g_csr + g_off[idx];
        int cnt = g_degin[idx];

        float4 a0 = make_float4(0.f, 0.f, 0.f, 0.f);
        float4 a1 = make_float4(0.f, 0.f, 0.f, 0.f);
        int j = 0;
        for (; j + 4 <= cnt; j += 4) {
            float2 e0 = __ldcs(&eb[j]);
            float2 e1 = __ldcs(&eb[j + 1]);
            float2 e2 = __ldcs(&eb[j + 2]);
            float2 e3 = __ldcs(&eb[j + 3]);
            const float4 v0 = *(const float4*)(h + (size_t)__float_as_int(e0.x) * DD + co);
            const float4 v1 = *(const float4*)(h + (size_t)__float_as_int(e1.x) * DD + co);
            const float4 v2 = *(const float4*)(h + (size_t)__float_as_int(e2.x) * DD + co);
            const float4 v3 = *(const float4*)(h + (size_t)__float_as_int(e3.x) * DD + co);
            a0.x += v0.x * e0.y; a0.y += v0.y * e0.y; a0.z += v0.z * e0.y; a0.w += v0.w * e0.y;
            a1.x += v1.x * e1.y; a1.y += v1.y * e1.y; a1.z += v1.z * e1.y; a1.w += v1.w * e1.y;
            a0.x += v2.x * e2.y; a0.y += v2.y * e2.y; a0.z += v2.z * e2.y; a0.w += v2.w * e2.y;
            a1.x += v3.x * e3.y; a1.y += v3.y * e3.y; a1.z += v3.z * e3.y; a1.w += v3.w * e3.y;
        }
        for (; j < cnt; j++) {
            float2 e0 = __ldcs(&eb[j]);
            const float4 v0 = *(const float4*)(h + (size_t)__float_as_int(e0.x) * DD + co);
            a0.x += v0.x * e0.y; a0.y += v0.y * e0.y; a0.z += v0.z * e0.y; a0.w += v0.w * e0.y;
        }
        a0.x += a1.x; a0.y += a1.y; a0.z += a1.z; a0.w += a1.w;
        __stcs((float4*)(aggrow + r * DD + co), a0);
    }
}

// ---------------- fused GEMM: out = relu(agg[N,512] @ W[512,128] + bsum) -----
// tf32x3 wmma; block = 64 rows x 128 cols; K chunked by 16 (32 chunks).
__global__ __launch_bounds__(256) void gemm512_kernel(
    const float* __restrict__ W, const float* __restrict__ b,
    float* __restrict__ out)
{
    __shared__ float smem[64 * 132];           // epilogue staging (reused)
    __shared__ float sAh[64][20], sAl[64][20];
    __shared__ float sBh[16][132], sBl[16][132];

    const int row0 = blockIdx.x * 64;
    const int tid = threadIdx.x;
    const int wid = tid >> 5;
    const int wr = wid & 3;
    const int wc = wid >> 2;

    wmma::fragment<wmma::accumulator, 16, 16, 8, float> acc[4];
#pragma unroll
    for (int i = 0; i < 4; i++) wmma::fill_fragment(acc[i], 0.f);

    for (int kc = 0; kc < KK; kc += 16) {
#pragma unroll
        for (int t = tid; t < 64 * 16; t += 256) {
            int rr = t >> 4, kk = t & 15;
            float a = g_agg[(size_t)(row0 + rr) * KK + kc + kk];
            float hi = wmma::__float_to_tf32(a);
            sAh[rr][kk] = hi;
            sAl[rr][kk] = wmma::__float_to_tf32(a - hi);
        }
#pragma unroll
        for (int t = tid; t < 16 * 128; t += 256) {
            int rr = t >> 7, j = t & 127;
            float v = W[(size_t)(kc + rr) * DD + j];
            float hi = wmma::__float_to_tf32(v);
            sBh[rr][j] = hi;
            sBl[rr][j] = wmma::__float_to_tf32(v - hi);
        }
        __syncthreads();

#pragma unroll
        for (int ks = 0; ks < 2; ks++) {
            wmma::fragment<wmma::matrix_a, 16, 16, 8, wmma::precision::tf32, wmma::row_major> ah, al;
            wmma::load_matrix_sync(ah, &sAh[wr * 16][ks * 8], 20);
            wmma::load_matrix_sync(al, &sAl[wr * 16][ks * 8], 20);
#pragma unroll
            for (int cg = 0; cg < 4; cg++) {
                int col = wc * 64 + cg * 16;
                wmma::fragment<wmma::matrix_b, 16, 16, 8, wmma::precision::tf32, wmma::row_major> bh, bl;
                wmma::load_matrix_sync(bh, &sBh[ks * 8][col], 132);
                wmma::load_matrix_sync(bl, &sBl[ks * 8][col], 132);
                wmma::mma_sync(acc[cg], ah, bh, acc[cg]);
                wmma::mma_sync(acc[cg], ah, bl, acc[cg]);
                wmma::mma_sync(acc[cg], al, bh, acc[cg]);
            }
        }
        __syncthreads();
    }

    // epilogue: stage to smem, add summed bias, relu, store (guard pad rows)
#pragma unroll
    for (int cg = 0; cg < 4; cg++)
        wmma::store_matrix_sync(smem + (wr * 16) * 132 + wc * 64 + cg * 16,
                                acc[cg], 132, wmma::mem_row_major);
    __syncthreads();

#pragma unroll
    for (int t = tid; t < 64 * 32; t += 256) {
        int rr = t >> 5;
        int c4 = (t & 31) * 4;
        int row = row0 + rr;
        if (row < NN) {
            float4 v = *(const float4*)(smem + rr * 132 + c4);
            v.x = fmaxf(v.x + b[c4]     + b[DD + c4]     + b[2*DD + c4]     + b[3*DD + c4],     0.f);
            v.y = fmaxf(v.y + b[c4 + 1] + b[DD + c4 + 1] + b[2*DD + c4 + 1] + b[3*DD + c4 + 1], 0.f);
            v.z = fmaxf(v.z + b[c4 + 2] + b[DD + c4 + 2] + b[2*DD + c4 + 2] + b[3*DD + c4 + 2], 0.f);
            v.w = fmaxf(v.w + b[c4 + 3] + b[DD + c4 + 3] + b[2*DD + c4 + 3] + b[3*DD + c4 + 3], 0.f);
            *(float4*)(out + (size_t)row * DD + c4) = v;
        }
    }
}

// ---------------- launch ----------------------------------------------------

extern "C" void kernel_launch(void* const* d_in, const int* in_sizes, int n_in,
                              void* d_out, int out_size)
{
    const float* x   = (const float*)d_in[0];
    const int*   src = (const int*)d_in[1];
    const int*   dst = (const int*)d_in[2];
    const float* ew  = (const float*)d_in[3];
    const float* W1  = (const float*)d_in[4];   // [R,D,D] == stacked [512,128]
    const float* b1  = (const float*)d_in[5];
    const float* W2  = (const float*)d_in[6];
    const float* b2  = (const float*)d_in[7];
    float* out = (float*)d_out;

    const int T = 256;
    const long long RE = (long long)RR * EE;
    const int edge_blocks = (int)((RE + T - 1) / T);

    // ---- setup (graph identical for both layers) ----
    zero_deg_kernel<<<(SCAN_N + T - 1) / T, T>>>();
    deg_kernel<<<edge_blocks, T>>>(src, dst);
    rsqrt_kernel<<<(SCAN_N + T - 1) / T, T>>>();
    scan_a_kernel<<<SCAN_NBLK, SCAN_BLK>>>();
    scan_b_kernel<<<1, 1024>>>();
    scan_c_kernel<<<SCAN_NBLK, SCAN_BLK>>>();
    fill_kernel<<<edge_blocks, T>>>(src, dst, ew);

    const int pull_blocks = (NP * 32 + T - 1) / T;
    const int ggrid = NP / 64;

    // ---- layer 1 ----
    pull_all_kernel<<<pull_blocks, T>>>(x);
    gemm512_kernel<<<ggrid, T>>>(W1, b1, g_h1);

    // ---- layer 2 ----
    pull_all_kernel<<<pull_blocks, T>>>(g_h1);
    gemm512_kernel<<<ggrid, T>>>(W2, b2, out);
}

// round 8
// speedup vs baseline: 6.4835x; 6.4835x over previous
#include <cuda_runtime.h>
#include <cuda_fp16.h>
#include <mma.h>
#include <cstdint>

using namespace nvcuda;

#define NN 100000
#define NP 100032            // padded to multiple of 64
#define DD 128
#define EE 1600000
#define RR 4

#define SCAN_N   (RR * NN)
#define SCAN_BLK 512
#define SCAN_NBLK ((SCAN_N + SCAN_BLK - 1) / SCAN_BLK)

// ---------------- device scratch --------------------------------------------
__device__ __half  g_Yh[(size_t)NP * DD];      // transformed feats (fp16, 25.6MB)
__device__ float   g_h1[(size_t)NN * DD];      // layer-1 output
__device__ float   g_acc[(size_t)NN * DD];     // aggregation accumulator
__device__ int     g_degout[SCAN_N];
__device__ int     g_degin[SCAN_N];
__device__ float   g_rdout[SCAN_N];
__device__ float   g_rdin[SCAN_N];
__device__ int     g_off[SCAN_N];
__device__ int     g_cur[SCAN_N];
__device__ int     g_bsum[SCAN_NBLK];
__device__ float2  g_csr[(size_t)RR * EE];     // (src bits, weight)

// ---------------- setup kernels ---------------------------------------------

__global__ void zero_deg_kernel() {
    int i = blockIdx.x * blockDim.x + threadIdx.x;
    if (i < SCAN_N) { g_degout[i] = 0; g_degin[i] = 0; }
}

__global__ void deg_kernel(const int* __restrict__ src, const int* __restrict__ dst) {
    long long i = (long long)blockIdx.x * blockDim.x + threadIdx.x;
    if (i >= (long long)RR * EE) return;
    int r = (int)(i / EE);
    atomicAdd(&g_degout[r * NN + src[i]], 1);
    atomicAdd(&g_degin[r * NN + dst[i]], 1);
}

__global__ void rsqrt_kernel() {
    int i = blockIdx.x * blockDim.x + threadIdx.x;
    if (i >= SCAN_N) return;
    g_rdout[i] = rsqrtf(fmaxf((float)g_degout[i], 1.f));
    g_rdin[i]  = rsqrtf(fmaxf((float)g_degin[i], 1.f));
}

__global__ void scan_a_kernel() {
    __shared__ int s[SCAN_BLK];
    int i = blockIdx.x * SCAN_BLK + threadIdx.x;
    s[threadIdx.x] = (i < SCAN_N) ? g_degin[i] : 0;
    __syncthreads();
    for (int d = SCAN_BLK / 2; d > 0; d >>= 1) {
        if (threadIdx.x < d) s[threadIdx.x] += s[threadIdx.x + d];
        __syncthreads();
    }
    if (threadIdx.x == 0) g_bsum[blockIdx.x] = s[0];
}

__global__ void scan_b_kernel() {
    __shared__ int s[1024];
    int t = threadIdx.x;
    s[t] = (t < SCAN_NBLK) ? g_bsum[t] : 0;
    __syncthreads();
    for (int d = 1; d < 1024; d <<= 1) {
        int v = (t >= d) ? s[t - d] : 0;
        __syncthreads();
        s[t] += v;
        __syncthreads();
    }
    if (t < SCAN_NBLK) g_bsum[t] = (t == 0) ? 0 : s[t - 1];
}

__global__ void scan_c_kernel() {
    __shared__ int s[SCAN_BLK];
    int i = blockIdx.x * SCAN_BLK + threadIdx.x;
    int v = (i < SCAN_N) ? g_degin[i] : 0;
    s[threadIdx.x] = v;
    __syncthreads();
    for (int d = 1; d < SCAN_BLK; d <<= 1) {
        int u = (threadIdx.x >= d) ? s[threadIdx.x - d] : 0;
        __syncthreads();
        s[threadIdx.x] += u;
        __syncthreads();
    }
    if (i < SCAN_N) {
        int ex = s[threadIdx.x] - v + g_bsum[blockIdx.x];
        g_off[i] = ex;
        g_cur[i] = ex;
    }
}

__global__ void fill_kernel(const int* __restrict__ src, const int* __restrict__ dst,
                            const float* __restrict__ ew) {
    long long i = (long long)blockIdx.x * blockDim.x + threadIdx.x;
    if (i >= (long long)RR * EE) return;
    int r = (int)(i / EE);
    int s = src[i], d = dst[i];
    float w = ew[i] * g_rdout[r * NN + s] * g_rdin[r * NN + d];
    int p = atomicAdd(&g_cur[r * NN + d], 1);
    g_csr[p] = make_float2(__int_as_float(s), w);
}

// ---------------- tf32x3 tensor-core GEMM: Yh = half(h @ W) ------------------
__global__ __launch_bounds__(256) void gemm_tf32_kernel(
    const float* __restrict__ h, const float* __restrict__ W)
{
    __shared__ float sAh[64][20], sAl[64][20];
    __shared__ float sBh[16][132], sBl[16][132];
    __shared__ float sStage[8][16][20];          // per-warp staging (ldm=20, mult of 4)

    const int row0 = blockIdx.x * 64;
    const int tid = threadIdx.x;
    const int wid = tid >> 5;
    const int lane = tid & 31;
    const int wr = wid & 3;
    const int wc = wid >> 2;

    wmma::fragment<wmma::accumulator, 16, 16, 8, float> acc[4];
#pragma unroll
    for (int i = 0; i < 4; i++) wmma::fill_fragment(acc[i], 0.f);

    for (int kc = 0; kc < DD; kc += 16) {
#pragma unroll
        for (int t = tid; t < 64 * 16; t += 256) {
            int rr = t >> 4, kk = t & 15;
            int n = row0 + rr;
            float a = (n < NN) ? h[(size_t)n * DD + kc + kk] : 0.f;
            float hi = wmma::__float_to_tf32(a);
            sAh[rr][kk] = hi;
            sAl[rr][kk] = wmma::__float_to_tf32(a - hi);
        }
#pragma unroll
        for (int t = tid; t < 16 * 128; t += 256) {
            int rr = t >> 7, j = t & 127;
            float b = W[(size_t)(kc + rr) * DD + j];
            float hi = wmma::__float_to_tf32(b);
            sBh[rr][j] = hi;
            sBl[rr][j] = wmma::__float_to_tf32(b - hi);
        }
        __syncthreads();

#pragma unroll
        for (int ks = 0; ks < 2; ks++) {
            wmma::fragment<wmma::matrix_a, 16, 16, 8, wmma::precision::tf32, wmma::row_major> ah, al;
            wmma::load_matrix_sync(ah, &sAh[wr * 16][ks * 8], 20);
            wmma::load_matrix_sync(al, &sAl[wr * 16][ks * 8], 20);
#pragma unroll
            for (int cg = 0; cg < 4; cg++) {
                int col = wc * 64 + cg * 16;
                wmma::fragment<wmma::matrix_b, 16, 16, 8, wmma::precision::tf32, wmma::row_major> bh, bl;
                wmma::load_matrix_sync(bh, &sBh[ks * 8][col], 132);
                wmma::load_matrix_sync(bl, &sBl[ks * 8][col], 132);
                wmma::mma_sync(acc[cg], ah, bh, acc[cg]);
                wmma::mma_sync(acc[cg], ah, bl, acc[cg]);
                wmma::mma_sync(acc[cg], al, bh, acc[cg]);
            }
        }
        __syncthreads();
    }

    // epilogue: per-warp stage each 16x16 tile, convert to half, store
    const int rr = lane >> 1;
    const int cb = (lane & 1) * 8;
#pragma unroll
    for (int cg = 0; cg < 4; cg++) {
        wmma::store_matrix_sync(&sStage[wid][0][0], acc[cg], 20, wmma::mem_row_major);
        __syncwarp();
        const float* sp = &sStage[wid][rr][cb];
        __half2 h0 = __floats2half2_rn(sp[0], sp[1]);
        __half2 h1 = __floats2half2_rn(sp[2], sp[3]);
        __half2 h2 = __floats2half2_rn(sp[4], sp[5]);
        __half2 h3 = __floats2half2_rn(sp[6], sp[7]);
        int grow = row0 + wr * 16 + rr;
        int gcol = wc * 64 + cg * 16 + cb;
        __half2 pack[4] = {h0, h1, h2, h3};
        *(uint4*)(g_Yh + (size_t)grow * DD + gcol) = *(const uint4*)pack;
        __syncwarp();
    }
}

// ---------------- per-relation pull: acc[n] (+)= sum_e Yh[src]*w -------------
// One warp per node; lane owns 4 cols (8B half gather per lane -> 256B/edge).
__global__ __launch_bounds__(256) void pull_r_kernel(int r, int first)
{
    int warp = (blockIdx.x * blockDim.x + threadIdx.x) >> 5;
    int lane = threadIdx.x & 31;
    if (warp >= NN) return;
    int idx = r * NN + warp;
    const float2* eb = g_csr + g_off[idx];
    int cnt = g_degin[idx];
    const int co = lane * 4;

    float4 a0 = make_float4(0.f, 0.f, 0.f, 0.f);
    float4 a1 = make_float4(0.f, 0.f, 0.f, 0.f);

    int j = 0;
    for (; j + 4 <= cnt; j += 4) {
        float2 e0 = eb[j],     e1 = eb[j + 1];
        float2 e2 = eb[j + 2], e3 = eb[j + 3];
        uint2 r0 = *(const uint2*)(g_Yh + (size_t)__float_as_int(e0.x) * DD + co);
        uint2 r1 = *(const uint2*)(g_Yh + (size_t)__float_as_int(e1.x) * DD + co);
        uint2 r2 = *(const uint2*)(g_Yh + (size_t)__float_as_int(e2.x) * DD + co);
        uint2 r3 = *(const uint2*)(g_Yh + (size_t)__float_as_int(e3.x) * DD + co);
        float2 f00 = __half22float2(*(__half2*)&r0.x), f01 = __half22float2(*(__half2*)&r0.y);
        float2 f10 = __half22float2(*(__half2*)&r1.x), f11 = __half22float2(*(__half2*)&r1.y);
        float2 f20 = __half22float2(*(__half2*)&r2.x), f21 = __half22float2(*(__half2*)&r2.y);
        float2 f30 = __half22float2(*(__half2*)&r3.x), f31 = __half22float2(*(__half2*)&r3.y);
        a0.x += f00.x * e0.y; a0.y += f00.y * e0.y; a0.z += f01.x * e0.y; a0.w += f01.y * e0.y;
        a1.x += f10.x * e1.y; a1.y += f10.y * e1.y; a1.z += f11.x * e1.y; a1.w += f11.y * e1.y;
        a0.x += f20.x * e2.y; a0.y += f20.y * e2.y; a0.z += f21.x * e2.y; a0.w += f21.y * e2.y;
        a1.x += f30.x * e3.y; a1.y += f30.y * e3.y; a1.z += f31.x * e3.y; a1.w += f31.y * e3.y;
    }
    for (; j < cnt; j++) {
        float2 e0 = eb[j];
        uint2 r0 = *(const uint2*)(g_Yh + (size_t)__float_as_int(e0.x) * DD + co);
        float2 f00 = __half22float2(*(__half2*)&r0.x), f01 = __half22float2(*(__half2*)&r0.y);
        a0.x += f00.x * e0.y; a0.y += f00.y * e0.y; a0.z += f01.x * e0.y; a0.w += f01.y * e0.y;
    }

    a0.x += a1.x; a0.y += a1.y; a0.z += a1.z; a0.w += a1.w;
    float* accp = g_acc + (size_t)warp * DD + co;
    if (!first) {
        float4 old = *(const float4*)accp;
        a0.x += old.x; a0.y += old.y; a0.z += old.z; a0.w += old.w;
    }
    *(float4*)accp = a0;
}

// out[n][j] = relu(acc[n][j] + sum_r b[r][j])
__global__ void bias_relu_kernel(const float* __restrict__ b, float* __restrict__ out) {
    int i = blockIdx.x * blockDim.x + threadIdx.x;
    if (i >= NN * DD) return;
    int j = i & (DD - 1);
    float bs = b[j] + b[DD + j] + b[2 * DD + j] + b[3 * DD + j];
    out[i] = fmaxf(g_acc[i] + bs, 0.f);
}

// ---------------- launch ----------------------------------------------------

extern "C" void kernel_launch(void* const* d_in, const int* in_sizes, int n_in,
                              void* d_out, int out_size)
{
    const float* x   = (const float*)d_in[0];
    const int*   src = (const int*)d_in[1];
    const int*   dst = (const int*)d_in[2];
    const float* ew  = (const float*)d_in[3];
    const float* W1  = (const float*)d_in[4];
    const float* b1  = (const float*)d_in[5];
    const float* W2  = (const float*)d_in[6];
    const float* b2  = (const float*)d_in[7];
    float* out = (float*)d_out;

    const int T = 256;
    const long long RE = (long long)RR * EE;
    const int edge_blocks = (int)((RE + T - 1) / T);

    // ---- setup (graph identical for both layers) ----
    zero_deg_kernel<<<(SCAN_N + T - 1) / T, T>>>();
    deg_kernel<<<edge_blocks, T>>>(src, dst);
    rsqrt_kernel<<<(SCAN_N + T - 1) / T, T>>>();
    scan_a_kernel<<<SCAN_NBLK, SCAN_BLK>>>();
    scan_b_kernel<<<1, 1024>>>();
    scan_c_kernel<<<SCAN_NBLK, SCAN_BLK>>>();
    fill_kernel<<<edge_blocks, T>>>(src, dst, ew);

    const int ggrid = NP / 64;
    const int pull_blocks = (NN * 32 + T - 1) / T;
    const int elem_blocks = (NN * DD + T - 1) / T;

    // ---- layer 1 ----
    for (int r = 0; r < RR; r++) {
        gemm_tf32_kernel<<<ggrid, T>>>(x, W1 + (size_t)r * DD * DD);
        pull_r_kernel<<<pull_blocks, T>>>(r, r == 0);
    }
    bias_relu_kernel<<<elem_blocks, T>>>(b1, g_h1);

    // ---- layer 2 ----
    for (int r = 0; r < RR; r++) {
        gemm_tf32_kernel<<<ggrid, T>>>(g_h1, W2 + (size_t)r * DD * DD);
        pull_r_kernel<<<pull_blocks, T>>>(r, r == 0);
    }
    bias_relu_kernel<<<elem_blocks, T>>>(b2, out);
}

// round 9
// speedup vs baseline: 6.5959x; 1.0173x over previous
#include <cuda_runtime.h>
#include <cuda_fp16.h>
#include <mma.h>
#include <cstdint>

using namespace nvcuda;

#define NN 100000
#define NP 100032            // padded to multiple of 64
#define DD 128
#define EE 1600000
#define RR 4

#define SCAN_N   (RR * NN)
#define SCAN_BLK 512
#define SCAN_NBLK ((SCAN_N + SCAN_BLK - 1) / SCAN_BLK)

// ---------------- device scratch --------------------------------------------
__device__ __half  g_Yh[(size_t)NP * DD];      // transformed feats (fp16, 25.6MB)
__device__ float   g_h1[(size_t)NN * DD];      // layer-1 output
__device__ float   g_acc[(size_t)NN * DD];     // aggregation accumulator
__device__ int     g_degout[SCAN_N];
__device__ int     g_degin[SCAN_N];
__device__ float   g_rdout[SCAN_N];
__device__ float   g_rdin[SCAN_N];
__device__ int     g_off[SCAN_N];
__device__ int     g_cur[SCAN_N];
__device__ int     g_bsum[SCAN_NBLK];
__device__ float2  g_csr[(size_t)RR * EE];     // (src bits, weight)

// ---------------- setup kernels ---------------------------------------------

__global__ void zero_deg_kernel() {
    int i = blockIdx.x * blockDim.x + threadIdx.x;
    if (i < SCAN_N) { g_degout[i] = 0; g_degin[i] = 0; }
}

__global__ void deg_kernel(const int* __restrict__ src, const int* __restrict__ dst) {
    long long i = (long long)blockIdx.x * blockDim.x + threadIdx.x;
    if (i >= (long long)RR * EE) return;
    int r = (int)(i / EE);
    atomicAdd(&g_degout[r * NN + src[i]], 1);
    atomicAdd(&g_degin[r * NN + dst[i]], 1);
}

__global__ void rsqrt_kernel() {
    int i = blockIdx.x * blockDim.x + threadIdx.x;
    if (i >= SCAN_N) return;
    g_rdout[i] = rsqrtf(fmaxf((float)g_degout[i], 1.f));
    g_rdin[i]  = rsqrtf(fmaxf((float)g_degin[i], 1.f));
}

__global__ void scan_a_kernel() {
    __shared__ int s[SCAN_BLK];
    int i = blockIdx.x * SCAN_BLK + threadIdx.x;
    s[threadIdx.x] = (i < SCAN_N) ? g_degin[i] : 0;
    __syncthreads();
    for (int d = SCAN_BLK / 2; d > 0; d >>= 1) {
        if (threadIdx.x < d) s[threadIdx.x] += s[threadIdx.x + d];
        __syncthreads();
    }
    if (threadIdx.x == 0) g_bsum[blockIdx.x] = s[0];
}

__global__ void scan_b_kernel() {
    __shared__ int s[1024];
    int t = threadIdx.x;
    s[t] = (t < SCAN_NBLK) ? g_bsum[t] : 0;
    __syncthreads();
    for (int d = 1; d < 1024; d <<= 1) {
        int v = (t >= d) ? s[t - d] : 0;
        __syncthreads();
        s[t] += v;
        __syncthreads();
    }
    if (t < SCAN_NBLK) g_bsum[t] = (t == 0) ? 0 : s[t - 1];
}

__global__ void scan_c_kernel() {
    __shared__ int s[SCAN_BLK];
    int i = blockIdx.x * SCAN_BLK + threadIdx.x;
    int v = (i < SCAN_N) ? g_degin[i] : 0;
    s[threadIdx.x] = v;
    __syncthreads();
    for (int d = 1; d < SCAN_BLK; d <<= 1) {
        int u = (threadIdx.x >= d) ? s[threadIdx.x - d] : 0;
        __syncthreads();
        s[threadIdx.x] += u;
        __syncthreads();
    }
    if (i < SCAN_N) {
        int ex = s[threadIdx.x] - v + g_bsum[blockIdx.x];
        g_off[i] = ex;
        g_cur[i] = ex;
    }
}

__global__ void fill_kernel(const int* __restrict__ src, const int* __restrict__ dst,
                            const float* __restrict__ ew) {
    long long i = (long long)blockIdx.x * blockDim.x + threadIdx.x;
    if (i >= (long long)RR * EE) return;
    int r = (int)(i / EE);
    int s = src[i], d = dst[i];
    float w = ew[i] * g_rdout[r * NN + s] * g_rdin[r * NN + d];
    int p = atomicAdd(&g_cur[r * NN + d], 1);
    g_csr[p] = make_float2(__int_as_float(s), w);
}

// ---------------- tf32x3 tensor-core GEMM: Yh = half(h @ W) ------------------
__global__ __launch_bounds__(256) void gemm_tf32_kernel(
    const float* __restrict__ h, const float* __restrict__ W)
{
    __shared__ float sAh[64][20], sAl[64][20];
    __shared__ float sBh[16][132], sBl[16][132];
    __shared__ float sStage[8][16][20];          // per-warp staging (ldm=20)

    const int row0 = blockIdx.x * 64;
    const int tid = threadIdx.x;
    const int wid = tid >> 5;
    const int lane = tid & 31;
    const int wr = wid & 3;
    const int wc = wid >> 2;

    wmma::fragment<wmma::accumulator, 16, 16, 8, float> acc[4];
#pragma unroll
    for (int i = 0; i < 4; i++) wmma::fill_fragment(acc[i], 0.f);

    for (int kc = 0; kc < DD; kc += 16) {
#pragma unroll
        for (int t = tid; t < 64 * 16; t += 256) {
            int rr = t >> 4, kk = t & 15;
            int n = row0 + rr;
            float a = (n < NN) ? h[(size_t)n * DD + kc + kk] : 0.f;
            float hi = wmma::__float_to_tf32(a);
            sAh[rr][kk] = hi;
            sAl[rr][kk] = wmma::__float_to_tf32(a - hi);
        }
#pragma unroll
        for (int t = tid; t < 16 * 128; t += 256) {
            int rr = t >> 7, j = t & 127;
            float b = W[(size_t)(kc + rr) * DD + j];
            float hi = wmma::__float_to_tf32(b);
            sBh[rr][j] = hi;
            sBl[rr][j] = wmma::__float_to_tf32(b - hi);
        }
        __syncthreads();

#pragma unroll
        for (int ks = 0; ks < 2; ks++) {
            wmma::fragment<wmma::matrix_a, 16, 16, 8, wmma::precision::tf32, wmma::row_major> ah, al;
            wmma::load_matrix_sync(ah, &sAh[wr * 16][ks * 8], 20);
            wmma::load_matrix_sync(al, &sAl[wr * 16][ks * 8], 20);
#pragma unroll
            for (int cg = 0; cg < 4; cg++) {
                int col = wc * 64 + cg * 16;
                wmma::fragment<wmma::matrix_b, 16, 16, 8, wmma::precision::tf32, wmma::row_major> bh, bl;
                wmma::load_matrix_sync(bh, &sBh[ks * 8][col], 132);
                wmma::load_matrix_sync(bl, &sBl[ks * 8][col], 132);
                wmma::mma_sync(acc[cg], ah, bh, acc[cg]);
                wmma::mma_sync(acc[cg], ah, bl, acc[cg]);
                wmma::mma_sync(acc[cg], al, bh, acc[cg]);
            }
        }
        __syncthreads();
    }

    const int rr = lane >> 1;
    const int cb = (lane & 1) * 8;
#pragma unroll
    for (int cg = 0; cg < 4; cg++) {
        wmma::store_matrix_sync(&sStage[wid][0][0], acc[cg], 20, wmma::mem_row_major);
        __syncwarp();
        const float* sp = &sStage[wid][rr][cb];
        __half2 h0 = __floats2half2_rn(sp[0], sp[1]);
        __half2 h1 = __floats2half2_rn(sp[2], sp[3]);
        __half2 h2 = __floats2half2_rn(sp[4], sp[5]);
        __half2 h3 = __floats2half2_rn(sp[6], sp[7]);
        int grow = row0 + wr * 16 + rr;
        int gcol = wc * 64 + cg * 16 + cb;
        __half2 pack[4] = {h0, h1, h2, h3};
        *(uint4*)(g_Yh + (size_t)grow * DD + gcol) = *(const uint4*)pack;
        __syncwarp();
    }
}

// ---------------- per-relation pull: acc[n] (+)= sum_e Yh[src]*w -------------
// Warp per node. Edge records loaded 32-at-a-time with ONE coalesced load,
// broadcast via shfl; gathers in the inner loop are mutually independent.
__global__ __launch_bounds__(256) void pull_r_kernel(int r, int first)
{
    int warp = (blockIdx.x * blockDim.x + threadIdx.x) >> 5;
    int lane = threadIdx.x & 31;
    if (warp >= NN) return;
    int idx = r * NN + warp;
    const float2* eb = g_csr + g_off[idx];
    int cnt = g_degin[idx];
    const int co = lane * 4;

    float4 a0 = make_float4(0.f, 0.f, 0.f, 0.f);

    for (int j = 0; j < cnt; j += 32) {
        int m = cnt - j; if (m > 32) m = 32;
        float2 er = (lane < m) ? eb[j + lane] : make_float2(0.f, 0.f);
        int si = __float_as_int(er.x);
#pragma unroll 8
        for (int k = 0; k < m; k++) {
            int s  = __shfl_sync(0xffffffffu, si, k);
            float w = __shfl_sync(0xffffffffu, er.y, k);
            uint2 rv = *(const uint2*)(g_Yh + (size_t)s * DD + co);
            float2 f0 = __half22float2(*(__half2*)&rv.x);
            float2 f1 = __half22float2(*(__half2*)&rv.y);
            a0.x += f0.x * w; a0.y += f0.y * w; a0.z += f1.x * w; a0.w += f1.y * w;
        }
    }

    float* accp = g_acc + (size_t)warp * DD + co;
    if (!first) {
        float4 old = *(const float4*)accp;
        a0.x += old.x; a0.y += old.y; a0.z += old.z; a0.w += old.w;
    }
    *(float4*)accp = a0;
}

// out[n][j] = relu(acc[n][j] + sum_r b[r][j])
__global__ void bias_relu_kernel(const float* __restrict__ b, float* __restrict__ out) {
    int i = blockIdx.x * blockDim.x + threadIdx.x;
    if (i >= NN * DD) return;
    int j = i & (DD - 1);
    float bs = b[j] + b[DD + j] + b[2 * DD + j] + b[3 * DD + j];
    out[i] = fmaxf(g_acc[i] + bs, 0.f);
}

// ---------------- launch ----------------------------------------------------

extern "C" void kernel_launch(void* const* d_in, const int* in_sizes, int n_in,
                              void* d_out, int out_size)
{
    const float* x   = (const float*)d_in[0];
    const int*   src = (const int*)d_in[1];
    const int*   dst = (const int*)d_in[2];
    const float* ew  = (const float*)d_in[3];
    const float* W1  = (const float*)d_in[4];
    const float* b1  = (const float*)d_in[5];
    const float* W2  = (const float*)d_in[6];
    const float* b2  = (const float*)d_in[7];
    float* out = (float*)d_out;

    const int T = 256;
    const long long RE = (long long)RR * EE;
    const int edge_blocks = (int)((RE + T - 1) / T);

    // ---- setup (graph identical for both layers) ----
    zero_deg_kernel<<<(SCAN_N + T - 1) / T, T>>>();
    deg_kernel<<<edge_blocks, T>>>(src, dst);
    rsqrt_kernel<<<(SCAN_N + T - 1) / T, T>>>();
    scan_a_kernel<<<SCAN_NBLK, SCAN_BLK>>>();
    scan_b_kernel<<<1, 1024>>>();
    scan_c_kernel<<<SCAN_NBLK, SCAN_BLK>>>();
    fill_kernel<<<edge_blocks, T>>>(src, dst, ew);

    const int ggrid = NP / 64;
    const int pull_blocks = (NN * 32 + T - 1) / T;
    const int elem_blocks = (NN * DD + T - 1) / T;

    // ---- layer 1 ----
    for (int r = 0; r < RR; r++) {
        gemm_tf32_kernel<<<ggrid, T>>>(x, W1 + (size_t)r * DD * DD);
        pull_r_kernel<<<pull_blocks, T>>>(r, r == 0);
    }
    bias_relu_kernel<<<elem_blocks, T>>>(b1, g_h1);

    // ---- layer 2 ----
    for (int r = 0; r < RR; r++) {
        gemm_tf32_kernel<<<ggrid, T>>>(g_h1, W2 + (size_t)r * DD * DD);
        pull_r_kernel<<<pull_blocks, T>>>(r, r == 0);
    }
    bias_relu_kernel<<<elem_blocks, T>>>(b2, out);
}